// round 14
// baseline (speedup 1.0000x reference)
#include <cuda_runtime.h>
#include <cuda_bf16.h>

// Problem constants
#define BB   32
#define TT   24
#define OO   128
#define HD   512
#define CTX  256
#define HOR  48
#define NB   (BB*OO)      // 4096 rows
#define RPB  32           // rows per block
#define NTH  256          // 8 warps: 4 rowblocks(8 rows) x 2 unit-columns(256 units)
#define NBLK (NB/RPB)     // 128 CTAs
#define SZH  (RPB*HD)     // floats per h buffer

// SMEM layout (floats): h[2][32][512] | gtab[512][12] | stt[32][2] | aux[2048]
#define SM_GTAB   (2*SZH)
#define SM_STT    (SM_GTAB + HD*12)
#define SM_AUX    (SM_STT + RPB*2)
#define SM_FLOATS (SM_AUX + 2048)
#define SMEM_BYTES (SM_FLOATS*4)

typedef unsigned long long u64;

// ---------------- device scratch (no allocations allowed) ----------------
__device__ __align__(16) float scr_Whr_enc[512*3*512];   // [uu][g][i][lane][4]
__device__ __align__(16) float scr_Whr_cell[512*3*512];
__device__ __align__(16) float scr_W1r[512*512];          // [uu][i][lane][4]
__device__ __align__(16) float scr_GI_enc[512*12];
__device__ __align__(16) float scr_GI_cell[512*12];
__device__ __align__(16) float scr_ctx[BB*HD];

// ---------------- packed fp32x2 helpers ----------------
__device__ __forceinline__ u64 ffma2(u64 a, u64 b, u64 c) {
    u64 d;
    asm("fma.rn.f32x2 %0, %1, %2, %3;" : "=l"(d) : "l"(a), "l"(b), "l"(c));
    return d;
}
__device__ __forceinline__ float f2sum(u64 v) {
    float lo, hi;
    asm("mov.b64 {%0,%1}, %2;" : "=f"(lo), "=f"(hi) : "l"(v));
    return lo + hi;
}
__device__ __forceinline__ float sigmoid_fast(float x) {
    return 1.f / (1.f + __expf(-x));
}
__device__ __forceinline__ float tanh_fast(float x) {
    float y;
    asm("tanh.approx.f32 %0, %1;" : "=f"(y) : "f"(x));
    return y;
}

// ---------------- prep kernels ----------------

// Reorder Wh_enc / Wh_cell / W1 into warp-coalesced [uu][g][i][lane][4] layout.
__global__ void prep_reorder(const float* __restrict__ Whe,
                             const float* __restrict__ Whc,
                             const float* __restrict__ W1) {
    int i = blockIdx.x * blockDim.x + threadIdx.x;
    if (i < 512*3*512) {
        int c    = i & 3;
        int lane = (i >> 2) & 31;
        int ii   = (i >> 7) & 127;
        int t    = i >> 14;          // uu*3 + g
        int g    = t % 3;
        int uu   = t / 3;
        int jj   = uu * 32 + lane;
        int k    = ii * 4 + c;
        size_t src = (size_t)(g * 512 + jj) * 512 + k;
        scr_Whr_enc[i]  = Whe[src];
        scr_Whr_cell[i] = Whc[src];
    }
    if (i < 512*512) {
        int c    = i & 3;
        int lane = (i >> 2) & 31;
        int ii   = (i >> 7) & 127;
        int uu   = i >> 14;
        int jj   = uu * 32 + lane;
        int k    = ii * 4 + c;
        scr_W1r[i] = W1[(size_t)jj * 512 + k];
    }
}

// Fold W_emb/b_emb into the input projections: gi = x @ (Wi@W_emb).T + (Wi@b_emb + bi)
__global__ void prep_gi(const float* __restrict__ Wi_enc, const float* __restrict__ bi_enc,
                        const float* __restrict__ bh_enc,
                        const float* __restrict__ Wi_cell, const float* __restrict__ bi_cell,
                        const float* __restrict__ bh_cell,
                        const float* __restrict__ W_emb, const float* __restrict__ b_emb) {
    int gwid = (blockIdx.x * blockDim.x + threadIdx.x) >> 5;
    int lane = threadIdx.x & 31;
    if (gwid >= 3072) return;
    int which = gwid / 1536;
    int rrow  = gwid % 1536;
    const float* Wi = which ? Wi_cell : Wi_enc;
    const float* bi = which ? bi_cell : bi_enc;
    const float* bh = which ? bh_cell : bh_enc;
    const float* wrow = Wi + (size_t)rrow * 512;
    float a0 = 0.f, a1 = 0.f, a2 = 0.f;
    for (int k = lane; k < 512; k += 32) {
        float w = wrow[k];
        a0 = fmaf(w, W_emb[2*k],   a0);
        a1 = fmaf(w, W_emb[2*k+1], a1);
        a2 = fmaf(w, b_emb[k],     a2);
    }
    for (int off = 16; off; off >>= 1) {
        a0 += __shfl_down_sync(0xffffffffu, a0, off);
        a1 += __shfl_down_sync(0xffffffffu, a1, off);
        a2 += __shfl_down_sync(0xffffffffu, a2, off);
    }
    if (lane == 0) {
        int g  = rrow >> 9;
        int jj = rrow & 511;
        float* G = (which ? scr_GI_cell : scr_GI_enc) + jj * 12;
        float c = a2 + bi[rrow];
        if (g == 0)      { G[0] = a0; G[1] = a1; G[2] = c + bh[rrow]; }
        else if (g == 1) { G[3] = a0; G[4] = a1; G[5] = c + bh[rrow]; }
        else             { G[6] = a0; G[7] = a1; G[8] = c; G[9] = bh[rrow]; }
    }
}

// ctx = z_ctx @ W_ctx.T + b_ctx   (32 x 512)
__global__ void prep_ctx(const float* __restrict__ z_ctx,
                         const float* __restrict__ W_ctx,
                         const float* __restrict__ b_ctx) {
    int idx = blockIdx.x * blockDim.x + threadIdx.x;
    if (idx >= BB * HD) return;
    int bb = idx >> 9;
    int j  = idx & 511;
    const float* z = z_ctx + bb * CTX;
    const float* w = W_ctx + (size_t)j * CTX;
    float a = 0.f;
    #pragma unroll 4
    for (int k = 0; k < CTX; k++) a = fmaf(z[k], w[k], a);
    scr_ctx[idx] = a + b_ctx[j];
}

// ---------------- fused GRU step ----------------
// 8 warps = 4 rowblocks (8 rows each) x 2 unit-columns (256 units each).
// Per warp: outer loop of 4 over pairs of 32-unit groups (u_in=2).
// Inner iter: 8 broadcast LDS (h) + 6 LDG.128 (weights) feed 96 FFMA2 —
// smem-return cost per FFMA2 drops 0.79 -> 0.58 vs previous layout.
__device__ __forceinline__ void gru_step(const float* __restrict__ hin,
                                         float* __restrict__ hout,
                                         const float* __restrict__ Wr,
                                         const float* __restrict__ gtab,
                                         const float* __restrict__ stt,
                                         int rbase, int lane, int ucol) {
    const ulonglong2* __restrict__ hb = (const ulonglong2*)(hin + rbase * HD);
    #pragma unroll 1
    for (int uo = 0; uo < 4; uo++) {
        int ugA = ucol * 8 + uo * 2;
        const ulonglong2* __restrict__ w0 = (const ulonglong2*)Wr + (size_t)(ugA * 3) * 4096 + lane;
        const ulonglong2* __restrict__ w1 = (const ulonglong2*)Wr + (size_t)((ugA + 1) * 3) * 4096 + lane;
        u64 a0r[8], a0z[8], a0n[8], a1r[8], a1z[8], a1n[8];
        #pragma unroll
        for (int r = 0; r < 8; r++) {
            a0r[r] = 0ull; a0z[r] = 0ull; a0n[r] = 0ull;
            a1r[r] = 0ull; a1z[r] = 0ull; a1n[r] = 0ull;
        }
        #pragma unroll 2
        for (int i = 0; i < 128; i++) {
            ulonglong2 v0r = w0[i * 32];
            ulonglong2 v0z = w0[4096 + i * 32];
            ulonglong2 v0n = w0[8192 + i * 32];
            ulonglong2 v1r = w1[i * 32];
            ulonglong2 v1z = w1[4096 + i * 32];
            ulonglong2 v1n = w1[8192 + i * 32];
            #pragma unroll
            for (int r = 0; r < 8; r++) {
                ulonglong2 hv = hb[r * 128 + i];
                a0r[r] = ffma2(hv.x, v0r.x, a0r[r]); a0r[r] = ffma2(hv.y, v0r.y, a0r[r]);
                a0z[r] = ffma2(hv.x, v0z.x, a0z[r]); a0z[r] = ffma2(hv.y, v0z.y, a0z[r]);
                a0n[r] = ffma2(hv.x, v0n.x, a0n[r]); a0n[r] = ffma2(hv.y, v0n.y, a0n[r]);
                a1r[r] = ffma2(hv.x, v1r.x, a1r[r]); a1r[r] = ffma2(hv.y, v1r.y, a1r[r]);
                a1z[r] = ffma2(hv.x, v1z.x, a1z[r]); a1z[r] = ffma2(hv.y, v1z.y, a1z[r]);
                a1n[r] = ffma2(hv.x, v1n.x, a1n[r]); a1n[r] = ffma2(hv.y, v1n.y, a1n[r]);
            }
        }
        #pragma unroll
        for (int g = 0; g < 2; g++) {
            int jj = (ugA + g) * 32 + lane;
            const float* gp = gtab + jj * 12;
            float m0r = gp[0], m1r = gp[1], cbr = gp[2];
            float m0z = gp[3], m1z = gp[4], cbz = gp[5];
            float m0n = gp[6], m1n = gp[7], cn  = gp[8], bhn = gp[9];
            #pragma unroll
            for (int r = 0; r < 8; r++) {
                int row = rbase + r;
                float x0 = stt[row * 2], x1 = stt[row * 2 + 1];
                float dr = f2sum(g ? a1r[r] : a0r[r]) + fmaf(x1, m1r, fmaf(x0, m0r, cbr));
                float dz = f2sum(g ? a1z[r] : a0z[r]) + fmaf(x1, m1z, fmaf(x0, m0z, cbz));
                float dn = f2sum(g ? a1n[r] : a0n[r]);
                float rg = sigmoid_fast(dr);
                float zg = sigmoid_fast(dz);
                float ng = tanh_fast(fmaf(x1, m1n, fmaf(x0, m0n, cn)) + rg * (dn + bhn));
                float hp = hin[row * HD + jj];
                hout[row * HD + jj] = ng + zg * (hp - ng);
            }
        }
    }
}

// ---------------- main persistent kernel ----------------
__global__ void __launch_bounds__(NTH, 1)
traj_main(const float* __restrict__ traj,
          const float* __restrict__ b1g,
          const float* __restrict__ W2g,
          const float* __restrict__ b2g,
          float* __restrict__ out) {
    extern __shared__ float sm[];
    float* hbuf = sm;
    float* gtab = sm + SM_GTAB;
    float* stt  = sm + SM_STT;
    float* aux  = sm + SM_AUX;

    int tid   = threadIdx.x;
    int lane  = tid & 31;
    int warp  = tid >> 5;
    int rbase = (warp & 3) * 8;  // 4 rowblocks of 8 rows
    int ucol  = warp >> 2;       // 2 unit-columns of 256 units
    int gRow0 = blockIdx.x * RPB;
    int b     = gRow0 >> 7;
    int o0    = gRow0 & 127;

    // init h = 0, load encoder gi table
    for (int i = tid; i < SZH; i += NTH) hbuf[i] = 0.f;
    for (int i = tid; i < HD * 12; i += NTH) gtab[i] = scr_GI_enc[i];
    __syncthreads();

    int cur = 0;
    // ---------------- encoder: 24 GRU steps ----------------
    for (int t = 0; t < TT; t++) {
        if (tid < RPB) {
            const float* p = traj + (((size_t)b * TT + t) * OO + o0 + tid) * 2;
            stt[tid * 2]     = p[0];
            stt[tid * 2 + 1] = p[1];
        }
        __syncthreads();
        gru_step(hbuf + cur * SZH, hbuf + (cur ^ 1) * SZH, scr_Whr_enc,
                 gtab, stt, rbase, lane, ucol);
        cur ^= 1;
        __syncthreads();
    }

    // ---------------- h += ctx; state0; switch tables ----------------
    for (int i = tid; i < HD; i += NTH) aux[i] = scr_ctx[b * HD + i];
    __syncthreads();
    {
        float* hc = hbuf + cur * SZH;
        for (int i = tid; i < SZH; i += NTH) hc[i] += aux[i & (HD - 1)];
    }
    if (tid < RPB) {
        const float* p = traj + (((size_t)b * TT + (TT - 1)) * OO + o0 + tid) * 2;
        stt[tid * 2]     = p[0];
        stt[tid * 2 + 1] = p[1];
    }
    __syncthreads();
    for (int i = tid; i < HD * 12; i += NTH) gtab[i] = scr_GI_cell[i];
    for (int i = tid; i < HD; i += NTH)      aux[i] = b1g[i];
    for (int i = tid; i < 2 * HD; i += NTH)  aux[HD + i] = W2g[i];
    if (tid < 2) aux[3 * HD + tid] = b2g[tid];
    __syncthreads();

    // ---------------- decoder: 48 steps ----------------
    for (int s = 0; s < HOR; s++) {
        gru_step(hbuf + cur * SZH, hbuf + (cur ^ 1) * SZH, scr_Whr_cell,
                 gtab, stt, rbase, lane, ucol);
        cur ^= 1;
        __syncthreads();

        const float* h  = hbuf + cur * SZH;
        float*      act = hbuf + (cur ^ 1) * SZH;

        // h1 = gelu(h @ W1.T + b1): per warp 8 rows x 8 ug, u_in=4
        const ulonglong2* __restrict__ hb = (const ulonglong2*)(h + rbase * HD);
        #pragma unroll 1
        for (int uo = 0; uo < 2; uo++) {
            int ugA = ucol * 8 + uo * 4;
            const ulonglong2* __restrict__ wp0 = (const ulonglong2*)scr_W1r + (size_t)(ugA + 0) * 4096 + lane;
            const ulonglong2* __restrict__ wp1 = (const ulonglong2*)scr_W1r + (size_t)(ugA + 1) * 4096 + lane;
            const ulonglong2* __restrict__ wp2 = (const ulonglong2*)scr_W1r + (size_t)(ugA + 2) * 4096 + lane;
            const ulonglong2* __restrict__ wp3 = (const ulonglong2*)scr_W1r + (size_t)(ugA + 3) * 4096 + lane;
            u64 a0[8], a1[8], a2[8], a3[8];
            #pragma unroll
            for (int r = 0; r < 8; r++) { a0[r] = 0ull; a1[r] = 0ull; a2[r] = 0ull; a3[r] = 0ull; }
            #pragma unroll 2
            for (int i = 0; i < 128; i++) {
                ulonglong2 w0 = wp0[i * 32];
                ulonglong2 w1 = wp1[i * 32];
                ulonglong2 w2 = wp2[i * 32];
                ulonglong2 w3 = wp3[i * 32];
                #pragma unroll
                for (int r = 0; r < 8; r++) {
                    ulonglong2 hv = hb[r * 128 + i];
                    a0[r] = ffma2(hv.x, w0.x, a0[r]); a0[r] = ffma2(hv.y, w0.y, a0[r]);
                    a1[r] = ffma2(hv.x, w1.x, a1[r]); a1[r] = ffma2(hv.y, w1.y, a1[r]);
                    a2[r] = ffma2(hv.x, w2.x, a2[r]); a2[r] = ffma2(hv.y, w2.y, a2[r]);
                    a3[r] = ffma2(hv.x, w3.x, a3[r]); a3[r] = ffma2(hv.y, w3.y, a3[r]);
                }
            }
            #pragma unroll
            for (int g = 0; g < 4; g++) {
                int jj = (ugA + g) * 32 + lane;
                float bb = aux[jj];
                #pragma unroll
                for (int r = 0; r < 8; r++) {
                    u64 av = (g == 0) ? a0[r] : (g == 1) ? a1[r] : (g == 2) ? a2[r] : a3[r];
                    float v = f2sum(av) + bb;
                    act[(rbase + r) * HD + jj] = 0.5f * v * (1.f + erff(v * 0.7071067811865475f));
                }
            }
        }
        __syncthreads();

        // d = h1 @ W2.T + b2 ; clamp/step/wrap ; emit  (8 warps x 4 rows)
        #pragma unroll
        for (int r = 0; r < 4; r++) {
            int row = warp * 4 + r;
            const float* hr = act + row * HD;
            float s0 = 0.f, s1 = 0.f;
            #pragma unroll
            for (int k = lane; k < HD; k += 32) {
                float hv = hr[k];
                s0 = fmaf(hv, aux[HD + k],     s0);
                s1 = fmaf(hv, aux[2 * HD + k], s1);
            }
            #pragma unroll
            for (int off = 16; off; off >>= 1) {
                s0 += __shfl_down_sync(0xffffffffu, s0, off);
                s1 += __shfl_down_sync(0xffffffffu, s1, off);
            }
            if (lane == 0) {
                float d0 = s0 + aux[3 * HD];
                float d1 = s1 + aux[3 * HD + 1];
                d0 = 2.f * tanhf(d0 * 0.5f);
                d1 = 2.f * tanhf(d1 * 0.5f);
                float n0 = stt[row * 2]     + d0;
                float n1 = stt[row * 2 + 1] + d1;
                n0 = fminf(fmaxf(n0, -90.f), 90.f);
                float m = fmodf(n1, 360.f);
                if (m < 0.f) m += 360.f;
                stt[row * 2]     = n0;
                stt[row * 2 + 1] = m;
                size_t oo = (((size_t)b * HOR + s) * OO + (o0 + row)) * 2;
                out[oo]     = n0;
                out[oo + 1] = m;
            }
        }
        __syncthreads();
    }
}

// ---------------- launch ----------------
extern "C" void kernel_launch(void* const* d_in, const int* in_sizes, int n_in,
                              void* d_out, int out_size) {
    (void)in_sizes; (void)n_in; (void)out_size;
    const float* z_ctx   = (const float*)d_in[0];
    const float* traj    = (const float*)d_in[1];
    const float* W_emb   = (const float*)d_in[2];
    const float* b_emb   = (const float*)d_in[3];
    const float* W_ctx   = (const float*)d_in[4];
    const float* b_ctx   = (const float*)d_in[5];
    const float* Wi_enc  = (const float*)d_in[6];
    const float* Wh_enc  = (const float*)d_in[7];
    const float* bi_enc  = (const float*)d_in[8];
    const float* bh_enc  = (const float*)d_in[9];
    const float* Wi_cell = (const float*)d_in[10];
    const float* Wh_cell = (const float*)d_in[11];
    const float* bi_cell = (const float*)d_in[12];
    const float* bh_cell = (const float*)d_in[13];
    const float* W1      = (const float*)d_in[14];
    const float* b1      = (const float*)d_in[15];
    const float* W2      = (const float*)d_in[16];
    const float* b2      = (const float*)d_in[17];
    float* out = (float*)d_out;

    prep_reorder<<<3072, 256>>>(Wh_enc, Wh_cell, W1);
    prep_gi<<<384, 256>>>(Wi_enc, bi_enc, bh_enc, Wi_cell, bi_cell, bh_cell, W_emb, b_emb);
    prep_ctx<<<64, 256>>>(z_ctx, W_ctx, b_ctx);

    cudaFuncSetAttribute(traj_main, cudaFuncAttributeMaxDynamicSharedMemorySize, SMEM_BYTES);
    traj_main<<<NBLK, NTH, SMEM_BYTES>>>(traj, b1, W2, b2, out);
}

// round 15
// speedup vs baseline: 1.0287x; 1.0287x over previous
#include <cuda_runtime.h>
#include <cuda_bf16.h>

// Problem constants
#define BB   32
#define TT   24
#define OO   128
#define HD   512
#define CTX  256
#define HOR  48
#define NB   (BB*OO)      // 4096 rows
#define RPB  32           // rows per block
#define NTH  256          // 8 warps: 4 rowblocks(8 rows) x 2 unit-columns(256 units)
#define NBLK (NB/RPB)     // 128 CTAs
#define SZH  (RPB*HD)     // floats per h buffer

// SMEM layout (floats): h[2][32][512] | gtab[512][12] | stt[32][2] | aux[2048]
#define SM_GTAB   (2*SZH)
#define SM_STT    (SM_GTAB + HD*12)
#define SM_AUX    (SM_STT + RPB*2)
#define SM_FLOATS (SM_AUX + 2048)
#define SMEM_BYTES (SM_FLOATS*4)

typedef unsigned long long u64;

// ---------------- device scratch (no allocations allowed) ----------------
__device__ __align__(16) float scr_Whr_enc[512*3*512];   // [uu][g][i][lane][4]
__device__ __align__(16) float scr_Whr_cell[512*3*512];
__device__ __align__(16) float scr_W1r[512*512];          // [uu][i][lane][4]
__device__ __align__(16) float scr_GI_enc[512*12];
__device__ __align__(16) float scr_GI_cell[512*12];
__device__ __align__(16) float scr_ctx[BB*HD];

// ---------------- packed fp32x2 helpers ----------------
__device__ __forceinline__ u64 ffma2(u64 a, u64 b, u64 c) {
    u64 d;
    asm("fma.rn.f32x2 %0, %1, %2, %3;" : "=l"(d) : "l"(a), "l"(b), "l"(c));
    return d;
}
__device__ __forceinline__ float f2sum(u64 v) {
    float lo, hi;
    asm("mov.b64 {%0,%1}, %2;" : "=f"(lo), "=f"(hi) : "l"(v));
    return lo + hi;
}
__device__ __forceinline__ float sigmoid_fast(float x) {
    return 1.f / (1.f + __expf(-x));
}
__device__ __forceinline__ float tanh_fast(float x) {
    float y;
    asm("tanh.approx.f32 %0, %1;" : "=f"(y) : "f"(x));
    return y;
}

// ---------------- prep kernels ----------------

// Reorder Wh_enc / Wh_cell / W1 into warp-coalesced [uu][g][i][lane][4] layout.
__global__ void prep_reorder(const float* __restrict__ Whe,
                             const float* __restrict__ Whc,
                             const float* __restrict__ W1) {
    int i = blockIdx.x * blockDim.x + threadIdx.x;
    if (i < 512*3*512) {
        int c    = i & 3;
        int lane = (i >> 2) & 31;
        int ii   = (i >> 7) & 127;
        int t    = i >> 14;          // uu*3 + g
        int g    = t % 3;
        int uu   = t / 3;
        int jj   = uu * 32 + lane;
        int k    = ii * 4 + c;
        size_t src = (size_t)(g * 512 + jj) * 512 + k;
        scr_Whr_enc[i]  = Whe[src];
        scr_Whr_cell[i] = Whc[src];
    }
    if (i < 512*512) {
        int c    = i & 3;
        int lane = (i >> 2) & 31;
        int ii   = (i >> 7) & 127;
        int uu   = i >> 14;
        int jj   = uu * 32 + lane;
        int k    = ii * 4 + c;
        scr_W1r[i] = W1[(size_t)jj * 512 + k];
    }
}

// Fold W_emb/b_emb into the input projections: gi = x @ (Wi@W_emb).T + (Wi@b_emb + bi)
__global__ void prep_gi(const float* __restrict__ Wi_enc, const float* __restrict__ bi_enc,
                        const float* __restrict__ bh_enc,
                        const float* __restrict__ Wi_cell, const float* __restrict__ bi_cell,
                        const float* __restrict__ bh_cell,
                        const float* __restrict__ W_emb, const float* __restrict__ b_emb) {
    int gwid = (blockIdx.x * blockDim.x + threadIdx.x) >> 5;
    int lane = threadIdx.x & 31;
    if (gwid >= 3072) return;
    int which = gwid / 1536;
    int rrow  = gwid % 1536;
    const float* Wi = which ? Wi_cell : Wi_enc;
    const float* bi = which ? bi_cell : bi_enc;
    const float* bh = which ? bh_cell : bh_enc;
    const float* wrow = Wi + (size_t)rrow * 512;
    float a0 = 0.f, a1 = 0.f, a2 = 0.f;
    for (int k = lane; k < 512; k += 32) {
        float w = wrow[k];
        a0 = fmaf(w, W_emb[2*k],   a0);
        a1 = fmaf(w, W_emb[2*k+1], a1);
        a2 = fmaf(w, b_emb[k],     a2);
    }
    for (int off = 16; off; off >>= 1) {
        a0 += __shfl_down_sync(0xffffffffu, a0, off);
        a1 += __shfl_down_sync(0xffffffffu, a1, off);
        a2 += __shfl_down_sync(0xffffffffu, a2, off);
    }
    if (lane == 0) {
        int g  = rrow >> 9;
        int jj = rrow & 511;
        float* G = (which ? scr_GI_cell : scr_GI_enc) + jj * 12;
        float c = a2 + bi[rrow];
        if (g == 0)      { G[0] = a0; G[1] = a1; G[2] = c + bh[rrow]; }
        else if (g == 1) { G[3] = a0; G[4] = a1; G[5] = c + bh[rrow]; }
        else             { G[6] = a0; G[7] = a1; G[8] = c; G[9] = bh[rrow]; }
    }
}

// ctx = z_ctx @ W_ctx.T + b_ctx   (32 x 512)
__global__ void prep_ctx(const float* __restrict__ z_ctx,
                         const float* __restrict__ W_ctx,
                         const float* __restrict__ b_ctx) {
    int idx = blockIdx.x * blockDim.x + threadIdx.x;
    if (idx >= BB * HD) return;
    int bb = idx >> 9;
    int j  = idx & 511;
    const float* z = z_ctx + bb * CTX;
    const float* w = W_ctx + (size_t)j * CTX;
    float a = 0.f;
    #pragma unroll 4
    for (int k = 0; k < CTX; k++) a = fmaf(z[k], w[k], a);
    scr_ctx[idx] = a + b_ctx[j];
}

// ---------------- fused GRU step ----------------
// 8 warps = 4 rowblocks (8 rows each) x 2 unit-columns (256 units each).
// Inner k-loop is ping-pong software-pipelined: weight LDGs for iteration i+1
// issue before the 48-FFMA2 body of iteration i, hiding the ~234-cycle L2
// weight latency that was the R14 stall source.
__device__ __forceinline__ void gru_step(const float* __restrict__ hin,
                                         float* __restrict__ hout,
                                         const float* __restrict__ Wr,
                                         const float* __restrict__ gtab,
                                         const float* __restrict__ stt,
                                         int rbase, int lane, int ucol) {
    const ulonglong2* __restrict__ hb = (const ulonglong2*)(hin + rbase * HD);
    #pragma unroll 1
    for (int uo = 0; uo < 4; uo++) {
        int ugA = ucol * 8 + uo * 2;
        const ulonglong2* __restrict__ w0 = (const ulonglong2*)Wr + (size_t)(ugA * 3) * 4096 + lane;
        const ulonglong2* __restrict__ w1 = w0 + 3 * 4096;
        u64 a0r[8], a0z[8], a0n[8], a1r[8], a1z[8], a1n[8];
        #pragma unroll
        for (int r = 0; r < 8; r++) {
            a0r[r] = 0ull; a0z[r] = 0ull; a0n[r] = 0ull;
            a1r[r] = 0ull; a1z[r] = 0ull; a1n[r] = 0ull;
        }
        // prologue: load i=0 into set A
        ulonglong2 A0r = w0[0], A0z = w0[4096], A0n = w0[8192];
        ulonglong2 A1r = w1[0], A1z = w1[4096], A1n = w1[8192];
        #pragma unroll 1
        for (int i = 0; i < 128; i += 2) {
            // prefetch i+1 into set B
            ulonglong2 B0r = w0[(i + 1) * 32];
            ulonglong2 B0z = w0[4096 + (i + 1) * 32];
            ulonglong2 B0n = w0[8192 + (i + 1) * 32];
            ulonglong2 B1r = w1[(i + 1) * 32];
            ulonglong2 B1z = w1[4096 + (i + 1) * 32];
            ulonglong2 B1n = w1[8192 + (i + 1) * 32];
            // body i (set A)
            #pragma unroll
            for (int r = 0; r < 8; r++) {
                ulonglong2 hv = hb[r * 128 + i];
                a0r[r] = ffma2(hv.x, A0r.x, a0r[r]); a0r[r] = ffma2(hv.y, A0r.y, a0r[r]);
                a0z[r] = ffma2(hv.x, A0z.x, a0z[r]); a0z[r] = ffma2(hv.y, A0z.y, a0z[r]);
                a0n[r] = ffma2(hv.x, A0n.x, a0n[r]); a0n[r] = ffma2(hv.y, A0n.y, a0n[r]);
                a1r[r] = ffma2(hv.x, A1r.x, a1r[r]); a1r[r] = ffma2(hv.y, A1r.y, a1r[r]);
                a1z[r] = ffma2(hv.x, A1z.x, a1z[r]); a1z[r] = ffma2(hv.y, A1z.y, a1z[r]);
                a1n[r] = ffma2(hv.x, A1n.x, a1n[r]); a1n[r] = ffma2(hv.y, A1n.y, a1n[r]);
            }
            // prefetch i+2 into set A (wraps harmlessly to 0 on last iter)
            int i2 = (i + 2) & 127;
            A0r = w0[i2 * 32];
            A0z = w0[4096 + i2 * 32];
            A0n = w0[8192 + i2 * 32];
            A1r = w1[i2 * 32];
            A1z = w1[4096 + i2 * 32];
            A1n = w1[8192 + i2 * 32];
            // body i+1 (set B)
            #pragma unroll
            for (int r = 0; r < 8; r++) {
                ulonglong2 hv = hb[r * 128 + i + 1];
                a0r[r] = ffma2(hv.x, B0r.x, a0r[r]); a0r[r] = ffma2(hv.y, B0r.y, a0r[r]);
                a0z[r] = ffma2(hv.x, B0z.x, a0z[r]); a0z[r] = ffma2(hv.y, B0z.y, a0z[r]);
                a0n[r] = ffma2(hv.x, B0n.x, a0n[r]); a0n[r] = ffma2(hv.y, B0n.y, a0n[r]);
                a1r[r] = ffma2(hv.x, B1r.x, a1r[r]); a1r[r] = ffma2(hv.y, B1r.y, a1r[r]);
                a1z[r] = ffma2(hv.x, B1z.x, a1z[r]); a1z[r] = ffma2(hv.y, B1z.y, a1z[r]);
                a1n[r] = ffma2(hv.x, B1n.x, a1n[r]); a1n[r] = ffma2(hv.y, B1n.y, a1n[r]);
            }
        }
        #pragma unroll
        for (int g = 0; g < 2; g++) {
            int jj = (ugA + g) * 32 + lane;
            const float* gp = gtab + jj * 12;
            float m0r = gp[0], m1r = gp[1], cbr = gp[2];
            float m0z = gp[3], m1z = gp[4], cbz = gp[5];
            float m0n = gp[6], m1n = gp[7], cn  = gp[8], bhn = gp[9];
            #pragma unroll
            for (int r = 0; r < 8; r++) {
                int row = rbase + r;
                float x0 = stt[row * 2], x1 = stt[row * 2 + 1];
                float dr = f2sum(g ? a1r[r] : a0r[r]) + fmaf(x1, m1r, fmaf(x0, m0r, cbr));
                float dz = f2sum(g ? a1z[r] : a0z[r]) + fmaf(x1, m1z, fmaf(x0, m0z, cbz));
                float dn = f2sum(g ? a1n[r] : a0n[r]);
                float rg = sigmoid_fast(dr);
                float zg = sigmoid_fast(dz);
                float ng = tanh_fast(fmaf(x1, m1n, fmaf(x0, m0n, cn)) + rg * (dn + bhn));
                float hp = hin[row * HD + jj];
                hout[row * HD + jj] = ng + zg * (hp - ng);
            }
        }
    }
}

// ---------------- main persistent kernel ----------------
__global__ void __launch_bounds__(NTH, 1)
traj_main(const float* __restrict__ traj,
          const float* __restrict__ b1g,
          const float* __restrict__ W2g,
          const float* __restrict__ b2g,
          float* __restrict__ out) {
    extern __shared__ float sm[];
    float* hbuf = sm;
    float* gtab = sm + SM_GTAB;
    float* stt  = sm + SM_STT;
    float* aux  = sm + SM_AUX;

    int tid   = threadIdx.x;
    int lane  = tid & 31;
    int warp  = tid >> 5;
    int rbase = (warp & 3) * 8;  // 4 rowblocks of 8 rows
    int ucol  = warp >> 2;       // 2 unit-columns of 256 units
    int gRow0 = blockIdx.x * RPB;
    int b     = gRow0 >> 7;
    int o0    = gRow0 & 127;

    // init h = 0, load encoder gi table
    for (int i = tid; i < SZH; i += NTH) hbuf[i] = 0.f;
    for (int i = tid; i < HD * 12; i += NTH) gtab[i] = scr_GI_enc[i];
    __syncthreads();

    int cur = 0;
    // ---------------- encoder: 24 GRU steps ----------------
    for (int t = 0; t < TT; t++) {
        if (tid < RPB) {
            const float* p = traj + (((size_t)b * TT + t) * OO + o0 + tid) * 2;
            stt[tid * 2]     = p[0];
            stt[tid * 2 + 1] = p[1];
        }
        __syncthreads();
        gru_step(hbuf + cur * SZH, hbuf + (cur ^ 1) * SZH, scr_Whr_enc,
                 gtab, stt, rbase, lane, ucol);
        cur ^= 1;
        __syncthreads();
    }

    // ---------------- h += ctx; state0; switch tables ----------------
    for (int i = tid; i < HD; i += NTH) aux[i] = scr_ctx[b * HD + i];
    __syncthreads();
    {
        float* hc = hbuf + cur * SZH;
        for (int i = tid; i < SZH; i += NTH) hc[i] += aux[i & (HD - 1)];
    }
    if (tid < RPB) {
        const float* p = traj + (((size_t)b * TT + (TT - 1)) * OO + o0 + tid) * 2;
        stt[tid * 2]     = p[0];
        stt[tid * 2 + 1] = p[1];
    }
    __syncthreads();
    for (int i = tid; i < HD * 12; i += NTH) gtab[i] = scr_GI_cell[i];
    for (int i = tid; i < HD; i += NTH)      aux[i] = b1g[i];
    for (int i = tid; i < 2 * HD; i += NTH)  aux[HD + i] = W2g[i];
    if (tid < 2) aux[3 * HD + tid] = b2g[tid];
    __syncthreads();

    // ---------------- decoder: 48 steps ----------------
    for (int s = 0; s < HOR; s++) {
        gru_step(hbuf + cur * SZH, hbuf + (cur ^ 1) * SZH, scr_Whr_cell,
                 gtab, stt, rbase, lane, ucol);
        cur ^= 1;
        __syncthreads();

        const float* h  = hbuf + cur * SZH;
        float*      act = hbuf + (cur ^ 1) * SZH;

        // h1 = gelu(h @ W1.T + b1): per warp 8 rows x 8 ug, u_in=4, ping-pong prefetch
        const ulonglong2* __restrict__ hb = (const ulonglong2*)(h + rbase * HD);
        #pragma unroll 1
        for (int uo = 0; uo < 2; uo++) {
            int ugA = ucol * 8 + uo * 4;
            const ulonglong2* __restrict__ wp0 = (const ulonglong2*)scr_W1r + (size_t)(ugA + 0) * 4096 + lane;
            const ulonglong2* __restrict__ wp1 = wp0 + 4096;
            const ulonglong2* __restrict__ wp2 = wp0 + 8192;
            const ulonglong2* __restrict__ wp3 = wp0 + 12288;
            u64 a0[8], a1[8], a2[8], a3[8];
            #pragma unroll
            for (int r = 0; r < 8; r++) { a0[r] = 0ull; a1[r] = 0ull; a2[r] = 0ull; a3[r] = 0ull; }
            ulonglong2 A0 = wp0[0], A1 = wp1[0], A2 = wp2[0], A3 = wp3[0];
            #pragma unroll 1
            for (int i = 0; i < 128; i += 2) {
                ulonglong2 B0 = wp0[(i + 1) * 32];
                ulonglong2 B1 = wp1[(i + 1) * 32];
                ulonglong2 B2 = wp2[(i + 1) * 32];
                ulonglong2 B3 = wp3[(i + 1) * 32];
                #pragma unroll
                for (int r = 0; r < 8; r++) {
                    ulonglong2 hv = hb[r * 128 + i];
                    a0[r] = ffma2(hv.x, A0.x, a0[r]); a0[r] = ffma2(hv.y, A0.y, a0[r]);
                    a1[r] = ffma2(hv.x, A1.x, a1[r]); a1[r] = ffma2(hv.y, A1.y, a1[r]);
                    a2[r] = ffma2(hv.x, A2.x, a2[r]); a2[r] = ffma2(hv.y, A2.y, a2[r]);
                    a3[r] = ffma2(hv.x, A3.x, a3[r]); a3[r] = ffma2(hv.y, A3.y, a3[r]);
                }
                int i2 = (i + 2) & 127;
                A0 = wp0[i2 * 32];
                A1 = wp1[i2 * 32];
                A2 = wp2[i2 * 32];
                A3 = wp3[i2 * 32];
                #pragma unroll
                for (int r = 0; r < 8; r++) {
                    ulonglong2 hv = hb[r * 128 + i + 1];
                    a0[r] = ffma2(hv.x, B0.x, a0[r]); a0[r] = ffma2(hv.y, B0.y, a0[r]);
                    a1[r] = ffma2(hv.x, B1.x, a1[r]); a1[r] = ffma2(hv.y, B1.y, a1[r]);
                    a2[r] = ffma2(hv.x, B2.x, a2[r]); a2[r] = ffma2(hv.y, B2.y, a2[r]);
                    a3[r] = ffma2(hv.x, B3.x, a3[r]); a3[r] = ffma2(hv.y, B3.y, a3[r]);
                }
            }
            #pragma unroll
            for (int g = 0; g < 4; g++) {
                int jj = (ugA + g) * 32 + lane;
                float bb = aux[jj];
                #pragma unroll
                for (int r = 0; r < 8; r++) {
                    u64 av = (g == 0) ? a0[r] : (g == 1) ? a1[r] : (g == 2) ? a2[r] : a3[r];
                    float v = f2sum(av) + bb;
                    act[(rbase + r) * HD + jj] = 0.5f * v * (1.f + erff(v * 0.7071067811865475f));
                }
            }
        }
        __syncthreads();

        // d = h1 @ W2.T + b2 ; clamp/step/wrap ; emit  (8 warps x 4 rows)
        #pragma unroll
        for (int r = 0; r < 4; r++) {
            int row = warp * 4 + r;
            const float* hr = act + row * HD;
            float s0 = 0.f, s1 = 0.f;
            #pragma unroll
            for (int k = lane; k < HD; k += 32) {
                float hv = hr[k];
                s0 = fmaf(hv, aux[HD + k],     s0);
                s1 = fmaf(hv, aux[2 * HD + k], s1);
            }
            #pragma unroll
            for (int off = 16; off; off >>= 1) {
                s0 += __shfl_down_sync(0xffffffffu, s0, off);
                s1 += __shfl_down_sync(0xffffffffu, s1, off);
            }
            if (lane == 0) {
                float d0 = s0 + aux[3 * HD];
                float d1 = s1 + aux[3 * HD + 1];
                d0 = 2.f * tanhf(d0 * 0.5f);
                d1 = 2.f * tanhf(d1 * 0.5f);
                float n0 = stt[row * 2]     + d0;
                float n1 = stt[row * 2 + 1] + d1;
                n0 = fminf(fmaxf(n0, -90.f), 90.f);
                float m = fmodf(n1, 360.f);
                if (m < 0.f) m += 360.f;
                stt[row * 2]     = n0;
                stt[row * 2 + 1] = m;
                size_t oo = (((size_t)b * HOR + s) * OO + (o0 + row)) * 2;
                out[oo]     = n0;
                out[oo + 1] = m;
            }
        }
        __syncthreads();
    }
}

// ---------------- launch ----------------
extern "C" void kernel_launch(void* const* d_in, const int* in_sizes, int n_in,
                              void* d_out, int out_size) {
    (void)in_sizes; (void)n_in; (void)out_size;
    const float* z_ctx   = (const float*)d_in[0];
    const float* traj    = (const float*)d_in[1];
    const float* W_emb   = (const float*)d_in[2];
    const float* b_emb   = (const float*)d_in[3];
    const float* W_ctx   = (const float*)d_in[4];
    const float* b_ctx   = (const float*)d_in[5];
    const float* Wi_enc  = (const float*)d_in[6];
    const float* Wh_enc  = (const float*)d_in[7];
    const float* bi_enc  = (const float*)d_in[8];
    const float* bh_enc  = (const float*)d_in[9];
    const float* Wi_cell = (const float*)d_in[10];
    const float* Wh_cell = (const float*)d_in[11];
    const float* bi_cell = (const float*)d_in[12];
    const float* bh_cell = (const float*)d_in[13];
    const float* W1      = (const float*)d_in[14];
    const float* b1      = (const float*)d_in[15];
    const float* W2      = (const float*)d_in[16];
    const float* b2      = (const float*)d_in[17];
    float* out = (float*)d_out;

    prep_reorder<<<3072, 256>>>(Wh_enc, Wh_cell, W1);
    prep_gi<<<384, 256>>>(Wi_enc, bi_enc, bh_enc, Wi_cell, bi_cell, bh_cell, W_emb, b_emb);
    prep_ctx<<<64, 256>>>(z_ctx, W_ctx, b_ctx);

    cudaFuncSetAttribute(traj_main, cudaFuncAttributeMaxDynamicSharedMemorySize, SMEM_BYTES);
    traj_main<<<NBLK, NTH, SMEM_BYTES>>>(traj, b1, W2, b2, out);
}

// round 16
// speedup vs baseline: 2.8473x; 2.7678x over previous
#include <cuda_runtime.h>
#include <cuda_bf16.h>

// Problem constants
#define BB   32
#define TT   24
#define OO   128
#define HD   512
#define CTX  256
#define HOR  48
#define NB   (BB*OO)      // 4096 rows
#define RPB  32           // rows per block
#define NTH  256          // 8 warps
#define NBLK (NB/RPB)     // 128 CTAs

// SMEM layout (bytes):
//  [0, 131072)        frag: uint4 [parity2][hi/lo2][mtile2][kt32][lane32]
//  [131072, 196608)   hm:   float [32][512] fp32 h master
//  [196608, 221184)   gtab: float [512][12]
//  [221184, 221440)   stt:  float [32][2]
//  [221440, 229664)   aux:  float [2056]  (b1 | W2 | b2 ; ctx staged at [0:512))
#define SMB_HM     131072
#define SMB_GTAB   196608
#define SMB_STT    221184
#define SMB_AUX    221440
#define SMEM_BYTES 229664
static_assert(SMEM_BYTES <= 232448, "smem over limit");

typedef unsigned int u32;

// ---------------- device scratch (no allocations allowed) ----------------
// Weight fragments: [ut][g][kt][lane] -> uint4 {bhi0, bhi1, blo0, blo1}
__device__ __align__(16) uint4 scr_Wf_enc [64*3*32*32];   // 3 MB
__device__ __align__(16) uint4 scr_Wf_cell[64*3*32*32];   // 3 MB
__device__ __align__(16) uint4 scr_Wf_w1  [64*32*32];     // 1 MB
__device__ __align__(16) float scr_GI_enc[512*12];
__device__ __align__(16) float scr_GI_cell[512*12];
__device__ __align__(16) float scr_ctx[BB*HD];

// ---------------- helpers ----------------
__device__ __forceinline__ float sigmoid_fast(float x) {
    return 1.f / (1.f + __expf(-x));
}
__device__ __forceinline__ float tanh_fast(float x) {
    float y;
    asm("tanh.approx.f32 %0, %1;" : "=f"(y) : "f"(x));
    return y;
}
// pack two floats to bf16x2 (a -> low half, b -> high half), exact rn rounding
__device__ __forceinline__ u32 packbf(float a, float b) {
    __nv_bfloat16 ba = __float2bfloat16(a), bb = __float2bfloat16(b);
    return ((u32)__bfloat16_as_ushort(bb) << 16) | (u32)__bfloat16_as_ushort(ba);
}
__device__ __forceinline__ float bf16res(float x) {  // x - bf16(x)
    return x - __bfloat162float(__float2bfloat16(x));
}
// m16n8k16 row.col bf16 MMA, fp32 accumulate
__device__ __forceinline__ void mma16816(float* c, const uint4& a, u32 b0, u32 b1) {
    asm volatile(
        "mma.sync.aligned.m16n8k16.row.col.f32.bf16.bf16.f32 "
        "{%0,%1,%2,%3}, {%4,%5,%6,%7}, {%8,%9}, {%0,%1,%2,%3};"
        : "+f"(c[0]), "+f"(c[1]), "+f"(c[2]), "+f"(c[3])
        : "r"(a.x), "r"(a.y), "r"(a.z), "r"(a.w), "r"(b0), "r"(b1));
}
__device__ __forceinline__ int fidx(int p, int hl, int m, int kt, int lane) {
    return (((p * 2 + hl) * 2 + m) * 32 + kt) * 32 + lane;
}

// ---------------- prep kernels ----------------

// Build B-fragments (PTX m16n8k16 col-major B layout) with bf16 hi/lo split.
// b0 holds B[k=(l%4)*2+{0,1}][n=l/4], b1 holds k+8. B[k][n] = Wh[j][k], j = gate row.
__global__ void prep_wfrag(const float* __restrict__ Whe,
                           const float* __restrict__ Whc,
                           const float* __restrict__ W1) {
    int idx = blockIdx.x * blockDim.x + threadIdx.x;
    const float* src;
    uint4* dst;
    int lane, kt, j;
    if (idx < 196608) {                       // enc: ((ut*3+g)*32+kt)*32+lane
        lane = idx & 31; kt = (idx >> 5) & 31;
        int rest = idx >> 10;                 // ut*3+g
        int g = rest % 3, ut = rest / 3;
        j = g * 512 + ut * 8 + (lane >> 2);
        src = Whe + (size_t)j * 512;
        dst = scr_Wf_enc + idx;
    } else if (idx < 393216) {                // cell
        int i2 = idx - 196608;
        lane = i2 & 31; kt = (i2 >> 5) & 31;
        int rest = i2 >> 10;
        int g = rest % 3, ut = rest / 3;
        j = g * 512 + ut * 8 + (lane >> 2);
        src = Whc + (size_t)j * 512;
        dst = scr_Wf_cell + i2;
    } else if (idx < 458752) {                // W1: ((ut)*32+kt)*32+lane
        int i2 = idx - 393216;
        lane = i2 & 31; kt = (i2 >> 5) & 31;
        int ut = i2 >> 10;
        j = ut * 8 + (lane >> 2);
        src = W1 + (size_t)j * 512;
        dst = scr_Wf_w1 + i2;
    } else return;
    int k0 = kt * 16 + (lane & 3) * 2;
    float w0 = src[k0], w1 = src[k0 + 1], w8 = src[k0 + 8], w9 = src[k0 + 9];
    uint4 v;
    v.x = packbf(w0, w1);
    v.y = packbf(w8, w9);
    v.z = packbf(bf16res(w0), bf16res(w1));
    v.w = packbf(bf16res(w8), bf16res(w9));
    *dst = v;
}

// Fold W_emb/b_emb into input projections (unchanged from prior rounds)
__global__ void prep_gi(const float* __restrict__ Wi_enc, const float* __restrict__ bi_enc,
                        const float* __restrict__ bh_enc,
                        const float* __restrict__ Wi_cell, const float* __restrict__ bi_cell,
                        const float* __restrict__ bh_cell,
                        const float* __restrict__ W_emb, const float* __restrict__ b_emb) {
    int gwid = (blockIdx.x * blockDim.x + threadIdx.x) >> 5;
    int lane = threadIdx.x & 31;
    if (gwid >= 3072) return;
    int which = gwid / 1536;
    int rrow  = gwid % 1536;
    const float* Wi = which ? Wi_cell : Wi_enc;
    const float* bi = which ? bi_cell : bi_enc;
    const float* bh = which ? bh_cell : bh_enc;
    const float* wrow = Wi + (size_t)rrow * 512;
    float a0 = 0.f, a1 = 0.f, a2 = 0.f;
    for (int k = lane; k < 512; k += 32) {
        float w = wrow[k];
        a0 = fmaf(w, W_emb[2*k],   a0);
        a1 = fmaf(w, W_emb[2*k+1], a1);
        a2 = fmaf(w, b_emb[k],     a2);
    }
    for (int off = 16; off; off >>= 1) {
        a0 += __shfl_down_sync(0xffffffffu, a0, off);
        a1 += __shfl_down_sync(0xffffffffu, a1, off);
        a2 += __shfl_down_sync(0xffffffffu, a2, off);
    }
    if (lane == 0) {
        int g  = rrow >> 9;
        int jj = rrow & 511;
        float* G = (which ? scr_GI_cell : scr_GI_enc) + jj * 12;
        float c = a2 + bi[rrow];
        if (g == 0)      { G[0] = a0; G[1] = a1; G[2] = c + bh[rrow]; }
        else if (g == 1) { G[3] = a0; G[4] = a1; G[5] = c + bh[rrow]; }
        else             { G[6] = a0; G[7] = a1; G[8] = c; G[9] = bh[rrow]; }
    }
}

__global__ void prep_ctx(const float* __restrict__ z_ctx,
                         const float* __restrict__ W_ctx,
                         const float* __restrict__ b_ctx) {
    int idx = blockIdx.x * blockDim.x + threadIdx.x;
    if (idx >= BB * HD) return;
    int bb = idx >> 9;
    int j  = idx & 511;
    const float* z = z_ctx + bb * CTX;
    const float* w = W_ctx + (size_t)j * CTX;
    float a = 0.f;
    #pragma unroll 4
    for (int k = 0; k < CTX; k++) a = fmaf(z[k], w[k], a);
    scr_ctx[idx] = a + b_ctx[j];
}

// ---------------- GRU step via tensor cores ----------------
// Warp w owns all 32 rows (both 16-row mtiles) and units [w*64, w*64+64), all 3 gates.
// 4 uchunks of 2 unit-tiles; per (uchunk, ktile): 4 LDS.128 (a hi/lo x mtiles),
// 6 LDG.128 (weight frags, hi+lo packed), 36 MMA (3 splits x 2 mtiles x 6 ntiles).
__device__ __forceinline__ void gru_step_mma(int p, uint4* __restrict__ frag,
                                             float* __restrict__ hm,
                                             const float* __restrict__ gtab,
                                             const float* __restrict__ stt,
                                             const uint4* __restrict__ Wf,
                                             int warp, int lane) {
    int q = 1 - p;
    #pragma unroll 1
    for (int uc = 0; uc < 4; uc++) {
        int T0 = warp * 8 + uc * 2;
        float d[2][2][3][4];
        #pragma unroll
        for (int t = 0; t < 2; t++)
            #pragma unroll
            for (int m = 0; m < 2; m++)
                #pragma unroll
                for (int g = 0; g < 3; g++)
                    #pragma unroll
                    for (int c = 0; c < 4; c++) d[t][m][g][c] = 0.f;
        #pragma unroll 2
        for (int kt = 0; kt < 32; kt++) {
            uint4 aH0 = frag[fidx(p, 0, 0, kt, lane)];
            uint4 aL0 = frag[fidx(p, 1, 0, kt, lane)];
            uint4 aH1 = frag[fidx(p, 0, 1, kt, lane)];
            uint4 aL1 = frag[fidx(p, 1, 1, kt, lane)];
            #pragma unroll
            for (int t = 0; t < 2; t++) {
                #pragma unroll
                for (int g = 0; g < 3; g++) {
                    uint4 w = Wf[(((size_t)(T0 + t) * 3 + g) * 32 + kt) * 32 + lane];
                    mma16816(d[t][0][g], aH0, w.x, w.y);
                    mma16816(d[t][0][g], aH0, w.z, w.w);
                    mma16816(d[t][0][g], aL0, w.x, w.y);
                    mma16816(d[t][1][g], aH1, w.x, w.y);
                    mma16816(d[t][1][g], aH1, w.z, w.w);
                    mma16816(d[t][1][g], aL1, w.x, w.y);
                }
            }
        }
        // epilogue: gates -> h_new -> hm + frag(q)
        int kt_out = warp * 4 + uc;
        #pragma unroll
        for (int t = 0; t < 2; t++) {
            int u = (T0 + t) * 8 + (lane & 3) * 2;
            const float* gA = gtab + u * 12;
            const float* gB = gtab + (u + 1) * 12;
            #pragma unroll
            for (int m = 0; m < 2; m++) {
                u32* fwH = (u32*)&frag[fidx(q, 0, m, kt_out, lane)];
                u32* fwL = (u32*)&frag[fidx(q, 1, m, kt_out, lane)];
                #pragma unroll
                for (int rh = 0; rh < 2; rh++) {
                    int row = m * 16 + (lane >> 2) + rh * 8;
                    float x0 = stt[row * 2], x1 = stt[row * 2 + 1];
                    float drA = d[t][m][0][rh*2+0] + fmaf(x1, gA[1], fmaf(x0, gA[0], gA[2]));
                    float dzA = d[t][m][1][rh*2+0] + fmaf(x1, gA[4], fmaf(x0, gA[3], gA[5]));
                    float dnA = d[t][m][2][rh*2+0];
                    float rgA = sigmoid_fast(drA), zgA = sigmoid_fast(dzA);
                    float ngA = tanh_fast(fmaf(x1, gA[7], fmaf(x0, gA[6], gA[8])) + rgA * (dnA + gA[9]));
                    float hpA = hm[row * 512 + u];
                    float hA  = ngA + zgA * (hpA - ngA);

                    float drB = d[t][m][0][rh*2+1] + fmaf(x1, gB[1], fmaf(x0, gB[0], gB[2]));
                    float dzB = d[t][m][1][rh*2+1] + fmaf(x1, gB[4], fmaf(x0, gB[3], gB[5]));
                    float dnB = d[t][m][2][rh*2+1];
                    float rgB = sigmoid_fast(drB), zgB = sigmoid_fast(dzB);
                    float ngB = tanh_fast(fmaf(x1, gB[7], fmaf(x0, gB[6], gB[8])) + rgB * (dnB + gB[9]));
                    float hpB = hm[row * 512 + u + 1];
                    float hB  = ngB + zgB * (hpB - ngB);

                    hm[row * 512 + u]     = hA;
                    hm[row * 512 + u + 1] = hB;
                    fwH[rh + 2 * t] = packbf(hA, hB);
                    fwL[rh + 2 * t] = packbf(bf16res(hA), bf16res(hB));
                }
            }
        }
    }
}

// ---------------- main persistent kernel ----------------
__global__ void __launch_bounds__(NTH, 1)
traj_main(const float* __restrict__ traj,
          const float* __restrict__ b1g,
          const float* __restrict__ W2g,
          const float* __restrict__ b2g,
          float* __restrict__ out) {
    extern __shared__ char smc[];
    uint4* frag = (uint4*)smc;
    float* hm   = (float*)(smc + SMB_HM);
    float* gtab = (float*)(smc + SMB_GTAB);
    float* stt  = (float*)(smc + SMB_STT);
    float* aux  = (float*)(smc + SMB_AUX);

    int tid  = threadIdx.x;
    int lane = tid & 31;
    int warp = tid >> 5;
    int gRow0 = blockIdx.x * RPB;
    int b  = gRow0 >> 7;
    int o0 = gRow0 & 127;

    // zero hm + both frag parities; load encoder gi table
    for (int i = tid; i < 16384; i += NTH) hm[i] = 0.f;
    {
        uint4 z4 = make_uint4(0, 0, 0, 0);
        for (int i = tid; i < 8192; i += NTH) frag[i] = z4;
    }
    for (int i = tid; i < HD * 12; i += NTH) gtab[i] = scr_GI_enc[i];
    __syncthreads();

    int cur = 0;
    // ---------------- encoder: 24 GRU steps ----------------
    for (int t = 0; t < TT; t++) {
        if (tid < RPB) {
            const float* p = traj + (((size_t)b * TT + t) * OO + o0 + tid) * 2;
            stt[tid * 2]     = p[0];
            stt[tid * 2 + 1] = p[1];
        }
        __syncthreads();
        gru_step_mma(cur, frag, hm, gtab, stt, scr_Wf_enc, warp, lane);
        cur ^= 1;
        __syncthreads();
    }

    // ---------------- h += ctx (update hm + frags in place at parity cur) ----------------
    for (int i = tid; i < HD; i += NTH) aux[i] = scr_ctx[b * HD + i];
    __syncthreads();
    #pragma unroll 1
    for (int uc = 0; uc < 4; uc++) {
        int kt_out = warp * 4 + uc;
        #pragma unroll
        for (int t = 0; t < 2; t++) {
            int u = (warp * 8 + uc * 2 + t) * 8 + (lane & 3) * 2;
            float cA = aux[u], cB = aux[u + 1];
            #pragma unroll
            for (int m = 0; m < 2; m++) {
                u32* fwH = (u32*)&frag[fidx(cur, 0, m, kt_out, lane)];
                u32* fwL = (u32*)&frag[fidx(cur, 1, m, kt_out, lane)];
                #pragma unroll
                for (int rh = 0; rh < 2; rh++) {
                    int row = m * 16 + (lane >> 2) + rh * 8;
                    float hA = hm[row * 512 + u]     + cA;
                    float hB = hm[row * 512 + u + 1] + cB;
                    hm[row * 512 + u]     = hA;
                    hm[row * 512 + u + 1] = hB;
                    fwH[rh + 2 * t] = packbf(hA, hB);
                    fwL[rh + 2 * t] = packbf(bf16res(hA), bf16res(hB));
                }
            }
        }
    }
    if (tid < RPB) {
        const float* p = traj + (((size_t)b * TT + (TT - 1)) * OO + o0 + tid) * 2;
        stt[tid * 2]     = p[0];
        stt[tid * 2 + 1] = p[1];
    }
    __syncthreads();
    // decoder tables
    for (int i = tid; i < HD * 12; i += NTH) gtab[i] = scr_GI_cell[i];
    for (int i = tid; i < HD; i += NTH)      aux[i] = b1g[i];
    for (int i = tid; i < 2 * HD; i += NTH)  aux[HD + i] = W2g[i];
    if (tid < 2) aux[3 * HD + tid] = b2g[tid];
    __syncthreads();

    // ---------------- decoder: 48 steps ----------------
    for (int s = 0; s < HOR; s++) {
        gru_step_mma(cur, frag, hm, gtab, stt, scr_Wf_cell, warp, lane);
        cur ^= 1;
        __syncthreads();

        // act scratch overlays the dead frag parity (old h)
        float* act = (float*)(smc + (cur ^ 1) * 65536);

        // h1 = gelu(h @ W1.T + b1) via mma; A = frag parity cur
        #pragma unroll 1
        for (int uc = 0; uc < 4; uc++) {
            int T0 = warp * 8 + uc * 2;
            float d[2][2][4];
            #pragma unroll
            for (int t = 0; t < 2; t++)
                #pragma unroll
                for (int m = 0; m < 2; m++)
                    #pragma unroll
                    for (int c = 0; c < 4; c++) d[t][m][c] = 0.f;
            #pragma unroll 2
            for (int kt = 0; kt < 32; kt++) {
                uint4 aH0 = frag[fidx(cur, 0, 0, kt, lane)];
                uint4 aL0 = frag[fidx(cur, 1, 0, kt, lane)];
                uint4 aH1 = frag[fidx(cur, 0, 1, kt, lane)];
                uint4 aL1 = frag[fidx(cur, 1, 1, kt, lane)];
                #pragma unroll
                for (int t = 0; t < 2; t++) {
                    uint4 w = scr_Wf_w1[(((size_t)(T0 + t)) * 32 + kt) * 32 + lane];
                    mma16816(d[t][0], aH0, w.x, w.y);
                    mma16816(d[t][0], aH0, w.z, w.w);
                    mma16816(d[t][0], aL0, w.x, w.y);
                    mma16816(d[t][1], aH1, w.x, w.y);
                    mma16816(d[t][1], aH1, w.z, w.w);
                    mma16816(d[t][1], aL1, w.x, w.y);
                }
            }
            #pragma unroll
            for (int t = 0; t < 2; t++) {
                int u = (T0 + t) * 8 + (lane & 3) * 2;
                float b1A = aux[u], b1B = aux[u + 1];
                #pragma unroll
                for (int m = 0; m < 2; m++) {
                    #pragma unroll
                    for (int rh = 0; rh < 2; rh++) {
                        int row = m * 16 + (lane >> 2) + rh * 8;
                        float v0 = d[t][m][rh*2+0] + b1A;
                        float v1 = d[t][m][rh*2+1] + b1B;
                        act[row * 512 + u]     = 0.5f * v0 * (1.f + erff(v0 * 0.7071067811865475f));
                        act[row * 512 + u + 1] = 0.5f * v1 * (1.f + erff(v1 * 0.7071067811865475f));
                    }
                }
            }
        }
        __syncthreads();

        // d = h1 @ W2.T + b2 ; clamp/step/wrap ; emit  (8 warps x 4 rows)
        #pragma unroll
        for (int r = 0; r < 4; r++) {
            int row = warp * 4 + r;
            const float* hr = act + row * HD;
            float s0 = 0.f, s1 = 0.f;
            #pragma unroll
            for (int k = lane; k < HD; k += 32) {
                float hv = hr[k];
                s0 = fmaf(hv, aux[HD + k],     s0);
                s1 = fmaf(hv, aux[2 * HD + k], s1);
            }
            #pragma unroll
            for (int off = 16; off; off >>= 1) {
                s0 += __shfl_down_sync(0xffffffffu, s0, off);
                s1 += __shfl_down_sync(0xffffffffu, s1, off);
            }
            if (lane == 0) {
                float d0 = s0 + aux[3 * HD];
                float d1 = s1 + aux[3 * HD + 1];
                d0 = 2.f * tanhf(d0 * 0.5f);
                d1 = 2.f * tanhf(d1 * 0.5f);
                float n0 = stt[row * 2]     + d0;
                float n1 = stt[row * 2 + 1] + d1;
                n0 = fminf(fmaxf(n0, -90.f), 90.f);
                float m = fmodf(n1, 360.f);
                if (m < 0.f) m += 360.f;
                stt[row * 2]     = n0;
                stt[row * 2 + 1] = m;
                size_t oo = (((size_t)b * HOR + s) * OO + (o0 + row)) * 2;
                out[oo]     = n0;
                out[oo + 1] = m;
            }
        }
        __syncthreads();
    }
}

// ---------------- launch ----------------
extern "C" void kernel_launch(void* const* d_in, const int* in_sizes, int n_in,
                              void* d_out, int out_size) {
    (void)in_sizes; (void)n_in; (void)out_size;
    const float* z_ctx   = (const float*)d_in[0];
    const float* traj    = (const float*)d_in[1];
    const float* W_emb   = (const float*)d_in[2];
    const float* b_emb   = (const float*)d_in[3];
    const float* W_ctx   = (const float*)d_in[4];
    const float* b_ctx   = (const float*)d_in[5];
    const float* Wi_enc  = (const float*)d_in[6];
    const float* Wh_enc  = (const float*)d_in[7];
    const float* bi_enc  = (const float*)d_in[8];
    const float* bh_enc  = (const float*)d_in[9];
    const float* Wi_cell = (const float*)d_in[10];
    const float* Wh_cell = (const float*)d_in[11];
    const float* bi_cell = (const float*)d_in[12];
    const float* bh_cell = (const float*)d_in[13];
    const float* W1      = (const float*)d_in[14];
    const float* b1      = (const float*)d_in[15];
    const float* W2      = (const float*)d_in[16];
    const float* b2      = (const float*)d_in[17];
    float* out = (float*)d_out;

    prep_wfrag<<<1792, 256>>>(Wh_enc, Wh_cell, W1);
    prep_gi<<<384, 256>>>(Wi_enc, bi_enc, bh_enc, Wi_cell, bi_cell, bh_cell, W_emb, b_emb);
    prep_ctx<<<64, 256>>>(z_ctx, W_ctx, b_ctx);

    cudaFuncSetAttribute(traj_main, cudaFuncAttributeMaxDynamicSharedMemorySize, SMEM_BYTES);
    traj_main<<<NBLK, NTH, SMEM_BYTES>>>(traj, b1, W2, b2, out);
}

// round 17
// speedup vs baseline: 2.9163x; 1.0242x over previous
#include <cuda_runtime.h>
#include <cuda_bf16.h>

// Problem constants
#define BB   32
#define TT   24
#define OO   128
#define HD   512
#define CTX  256
#define HOR  48
#define NB   (BB*OO)      // 4096 rows
#define RPB  32           // rows per block
#define NTH  512          // 16 warps
#define NBLK (NB/RPB)     // 128 CTAs
#define HMS  520          // padded hm row stride (floats) -> rows 8 banks apart

// SMEM layout (bytes):
//  [0, 131072)        frag: uint4 [parity2][hi/lo2][mtile2][kt32][lane32]
//  [131072, 197632)   hm:   float [32][520] fp32 h master (padded stride)
//  [197632, 222208)   gtab: float [512][12]
//  [222208, 222464)   stt:  float [32][2]
//  [222464, 230688)   aux:  float [2056]  (b1 | W2 | b2 ; ctx staged at [0:512))
#define SMB_HM     131072
#define SMB_GTAB   197632
#define SMB_STT    222208
#define SMB_AUX    222464
#define SMEM_BYTES 230688
static_assert(SMEM_BYTES <= 232448, "smem over limit");

typedef unsigned int u32;

// ---------------- device scratch (no allocations allowed) ----------------
// Weight fragments: [ut][g][kt][lane] -> uint4 {bhi0, bhi1, blo0, blo1}
__device__ __align__(16) uint4 scr_Wf_enc [64*3*32*32];   // 3 MB
__device__ __align__(16) uint4 scr_Wf_cell[64*3*32*32];   // 3 MB
__device__ __align__(16) uint4 scr_Wf_w1  [64*32*32];     // 1 MB
__device__ __align__(16) float scr_GI_enc[512*12];
__device__ __align__(16) float scr_GI_cell[512*12];
__device__ __align__(16) float scr_ctx[BB*HD];

// ---------------- helpers ----------------
__device__ __forceinline__ float sigmoid_fast(float x) {
    return 1.f / (1.f + __expf(-x));
}
__device__ __forceinline__ float tanh_fast(float x) {
    float y;
    asm("tanh.approx.f32 %0, %1;" : "=f"(y) : "f"(x));
    return y;
}
__device__ __forceinline__ u32 packbf(float a, float b) {
    __nv_bfloat16 ba = __float2bfloat16(a), bb = __float2bfloat16(b);
    return ((u32)__bfloat16_as_ushort(bb) << 16) | (u32)__bfloat16_as_ushort(ba);
}
__device__ __forceinline__ float bf16res(float x) {  // x - bf16(x)
    return x - __bfloat162float(__float2bfloat16(x));
}
__device__ __forceinline__ void mma16816(float* c, const uint4& a, u32 b0, u32 b1) {
    asm volatile(
        "mma.sync.aligned.m16n8k16.row.col.f32.bf16.bf16.f32 "
        "{%0,%1,%2,%3}, {%4,%5,%6,%7}, {%8,%9}, {%0,%1,%2,%3};"
        : "+f"(c[0]), "+f"(c[1]), "+f"(c[2]), "+f"(c[3])
        : "r"(a.x), "r"(a.y), "r"(a.z), "r"(a.w), "r"(b0), "r"(b1));
}
__device__ __forceinline__ int fidx(int p, int hl, int m, int kt, int lane) {
    return (((p * 2 + hl) * 2 + m) * 32 + kt) * 32 + lane;
}
// decoder act scratch: column rotation by row*8 breaks stride-512 bank pattern
__device__ __forceinline__ int actIdx(int row, int col) {
    return row * 512 + ((col + row * 8) & 511);
}

// ---------------- prep kernels ----------------

// Build B-fragments (PTX m16n8k16 col-major B layout) with bf16 hi/lo split.
__global__ void prep_wfrag(const float* __restrict__ Whe,
                           const float* __restrict__ Whc,
                           const float* __restrict__ W1) {
    int idx = blockIdx.x * blockDim.x + threadIdx.x;
    const float* src;
    uint4* dst;
    int lane, kt, j;
    if (idx < 196608) {                       // enc: ((ut*3+g)*32+kt)*32+lane
        lane = idx & 31; kt = (idx >> 5) & 31;
        int rest = idx >> 10;
        int g = rest % 3, ut = rest / 3;
        j = g * 512 + ut * 8 + (lane >> 2);
        src = Whe + (size_t)j * 512;
        dst = scr_Wf_enc + idx;
    } else if (idx < 393216) {                // cell
        int i2 = idx - 196608;
        lane = i2 & 31; kt = (i2 >> 5) & 31;
        int rest = i2 >> 10;
        int g = rest % 3, ut = rest / 3;
        j = g * 512 + ut * 8 + (lane >> 2);
        src = Whc + (size_t)j * 512;
        dst = scr_Wf_cell + i2;
    } else if (idx < 458752) {                // W1
        int i2 = idx - 393216;
        lane = i2 & 31; kt = (i2 >> 5) & 31;
        int ut = i2 >> 10;
        j = ut * 8 + (lane >> 2);
        src = W1 + (size_t)j * 512;
        dst = scr_Wf_w1 + i2;
    } else return;
    int k0 = kt * 16 + (lane & 3) * 2;
    float w0 = src[k0], w1 = src[k0 + 1], w8 = src[k0 + 8], w9 = src[k0 + 9];
    uint4 v;
    v.x = packbf(w0, w1);
    v.y = packbf(w8, w9);
    v.z = packbf(bf16res(w0), bf16res(w1));
    v.w = packbf(bf16res(w8), bf16res(w9));
    *dst = v;
}

// Fold W_emb/b_emb into input projections
__global__ void prep_gi(const float* __restrict__ Wi_enc, const float* __restrict__ bi_enc,
                        const float* __restrict__ bh_enc,
                        const float* __restrict__ Wi_cell, const float* __restrict__ bi_cell,
                        const float* __restrict__ bh_cell,
                        const float* __restrict__ W_emb, const float* __restrict__ b_emb) {
    int gwid = (blockIdx.x * blockDim.x + threadIdx.x) >> 5;
    int lane = threadIdx.x & 31;
    if (gwid >= 3072) return;
    int which = gwid / 1536;
    int rrow  = gwid % 1536;
    const float* Wi = which ? Wi_cell : Wi_enc;
    const float* bi = which ? bi_cell : bi_enc;
    const float* bh = which ? bh_cell : bh_enc;
    const float* wrow = Wi + (size_t)rrow * 512;
    float a0 = 0.f, a1 = 0.f, a2 = 0.f;
    for (int k = lane; k < 512; k += 32) {
        float w = wrow[k];
        a0 = fmaf(w, W_emb[2*k],   a0);
        a1 = fmaf(w, W_emb[2*k+1], a1);
        a2 = fmaf(w, b_emb[k],     a2);
    }
    for (int off = 16; off; off >>= 1) {
        a0 += __shfl_down_sync(0xffffffffu, a0, off);
        a1 += __shfl_down_sync(0xffffffffu, a1, off);
        a2 += __shfl_down_sync(0xffffffffu, a2, off);
    }
    if (lane == 0) {
        int g  = rrow >> 9;
        int jj = rrow & 511;
        float* G = (which ? scr_GI_cell : scr_GI_enc) + jj * 12;
        float c = a2 + bi[rrow];
        if (g == 0)      { G[0] = a0; G[1] = a1; G[2] = c + bh[rrow]; }
        else if (g == 1) { G[3] = a0; G[4] = a1; G[5] = c + bh[rrow]; }
        else             { G[6] = a0; G[7] = a1; G[8] = c; G[9] = bh[rrow]; }
    }
}

__global__ void prep_ctx(const float* __restrict__ z_ctx,
                         const float* __restrict__ W_ctx,
                         const float* __restrict__ b_ctx) {
    int idx = blockIdx.x * blockDim.x + threadIdx.x;
    if (idx >= BB * HD) return;
    int bb = idx >> 9;
    int j  = idx & 511;
    const float* z = z_ctx + bb * CTX;
    const float* w = W_ctx + (size_t)j * CTX;
    float a = 0.f;
    #pragma unroll 4
    for (int k = 0; k < CTX; k++) a = fmaf(z[k], w[k], a);
    scr_ctx[idx] = a + b_ctx[j];
}

// ---------------- GRU step via tensor cores ----------------
// 16 warps; warp owns all 32 rows and 4 unit-tiles (uc2 x t2), all 3 gates.
__device__ __forceinline__ void gru_step_mma(int p, uint4* __restrict__ frag,
                                             float* __restrict__ hm,
                                             const float* __restrict__ gtab,
                                             const float* __restrict__ stt,
                                             const uint4* __restrict__ Wf,
                                             int warp, int lane) {
    int q = 1 - p;
    #pragma unroll 1
    for (int uc = 0; uc < 2; uc++) {
        int T0 = warp * 4 + uc * 2;
        float d[2][2][3][4];
        #pragma unroll
        for (int t = 0; t < 2; t++)
            #pragma unroll
            for (int m = 0; m < 2; m++)
                #pragma unroll
                for (int g = 0; g < 3; g++)
                    #pragma unroll
                    for (int c = 0; c < 4; c++) d[t][m][g][c] = 0.f;
        #pragma unroll 1
        for (int kt = 0; kt < 32; kt++) {
            uint4 aH0 = frag[fidx(p, 0, 0, kt, lane)];
            uint4 aL0 = frag[fidx(p, 1, 0, kt, lane)];
            uint4 aH1 = frag[fidx(p, 0, 1, kt, lane)];
            uint4 aL1 = frag[fidx(p, 1, 1, kt, lane)];
            #pragma unroll
            for (int t = 0; t < 2; t++) {
                #pragma unroll
                for (int g = 0; g < 3; g++) {
                    uint4 w = Wf[(((size_t)(T0 + t) * 3 + g) * 32 + kt) * 32 + lane];
                    mma16816(d[t][0][g], aH0, w.x, w.y);
                    mma16816(d[t][0][g], aH0, w.z, w.w);
                    mma16816(d[t][0][g], aL0, w.x, w.y);
                    mma16816(d[t][1][g], aH1, w.x, w.y);
                    mma16816(d[t][1][g], aH1, w.z, w.w);
                    mma16816(d[t][1][g], aL1, w.x, w.y);
                }
            }
        }
        // epilogue: gates -> h_new -> hm + frag(q)
        int kt_out = warp * 2 + uc;
        #pragma unroll
        for (int t = 0; t < 2; t++) {
            int u = (T0 + t) * 8 + (lane & 3) * 2;
            const float* gA = gtab + u * 12;
            const float* gB = gtab + (u + 1) * 12;
            #pragma unroll
            for (int m = 0; m < 2; m++) {
                u32* fwH = (u32*)&frag[fidx(q, 0, m, kt_out, lane)];
                u32* fwL = (u32*)&frag[fidx(q, 1, m, kt_out, lane)];
                #pragma unroll
                for (int rh = 0; rh < 2; rh++) {
                    int row = m * 16 + (lane >> 2) + rh * 8;
                    float x0 = stt[row * 2], x1 = stt[row * 2 + 1];
                    float2 hp = *(float2*)&hm[row * HMS + u];
                    float drA = d[t][m][0][rh*2+0] + fmaf(x1, gA[1], fmaf(x0, gA[0], gA[2]));
                    float dzA = d[t][m][1][rh*2+0] + fmaf(x1, gA[4], fmaf(x0, gA[3], gA[5]));
                    float dnA = d[t][m][2][rh*2+0];
                    float rgA = sigmoid_fast(drA), zgA = sigmoid_fast(dzA);
                    float ngA = tanh_fast(fmaf(x1, gA[7], fmaf(x0, gA[6], gA[8])) + rgA * (dnA + gA[9]));
                    float hA  = ngA + zgA * (hp.x - ngA);

                    float drB = d[t][m][0][rh*2+1] + fmaf(x1, gB[1], fmaf(x0, gB[0], gB[2]));
                    float dzB = d[t][m][1][rh*2+1] + fmaf(x1, gB[4], fmaf(x0, gB[3], gB[5]));
                    float dnB = d[t][m][2][rh*2+1];
                    float rgB = sigmoid_fast(drB), zgB = sigmoid_fast(dzB);
                    float ngB = tanh_fast(fmaf(x1, gB[7], fmaf(x0, gB[6], gB[8])) + rgB * (dnB + gB[9]));
                    float hB  = ngB + zgB * (hp.y - ngB);

                    *(float2*)&hm[row * HMS + u] = make_float2(hA, hB);
                    fwH[rh + 2 * t] = packbf(hA, hB);
                    fwL[rh + 2 * t] = packbf(bf16res(hA), bf16res(hB));
                }
            }
        }
    }
}

// ---------------- main persistent kernel ----------------
__global__ void __launch_bounds__(NTH, 1)
traj_main(const float* __restrict__ traj,
          const float* __restrict__ b1g,
          const float* __restrict__ W2g,
          const float* __restrict__ b2g,
          float* __restrict__ out) {
    extern __shared__ char smc[];
    uint4* frag = (uint4*)smc;
    float* hm   = (float*)(smc + SMB_HM);
    float* gtab = (float*)(smc + SMB_GTAB);
    float* stt  = (float*)(smc + SMB_STT);
    float* aux  = (float*)(smc + SMB_AUX);

    int tid  = threadIdx.x;
    int lane = tid & 31;
    int warp = tid >> 5;
    int gRow0 = blockIdx.x * RPB;
    int b  = gRow0 >> 7;
    int o0 = gRow0 & 127;

    // zero hm + both frag parities; load encoder gi table
    for (int i = tid; i < 32 * HMS; i += NTH) hm[i] = 0.f;
    {
        uint4 z4 = make_uint4(0, 0, 0, 0);
        for (int i = tid; i < 8192; i += NTH) frag[i] = z4;
    }
    for (int i = tid; i < HD * 12; i += NTH) gtab[i] = scr_GI_enc[i];
    __syncthreads();

    int cur = 0;
    // ---------------- encoder: 24 GRU steps ----------------
    for (int t = 0; t < TT; t++) {
        if (tid < RPB) {
            const float* p = traj + (((size_t)b * TT + t) * OO + o0 + tid) * 2;
            stt[tid * 2]     = p[0];
            stt[tid * 2 + 1] = p[1];
        }
        __syncthreads();
        gru_step_mma(cur, frag, hm, gtab, stt, scr_Wf_enc, warp, lane);
        cur ^= 1;
        __syncthreads();
    }

    // ---------------- h += ctx (update hm + frags in place at parity cur) ----------------
    for (int i = tid; i < HD; i += NTH) aux[i] = scr_ctx[b * HD + i];
    __syncthreads();
    #pragma unroll 1
    for (int uc = 0; uc < 2; uc++) {
        int kt_out = warp * 2 + uc;
        #pragma unroll
        for (int t = 0; t < 2; t++) {
            int u = (warp * 4 + uc * 2 + t) * 8 + (lane & 3) * 2;
            float cA = aux[u], cB = aux[u + 1];
            #pragma unroll
            for (int m = 0; m < 2; m++) {
                u32* fwH = (u32*)&frag[fidx(cur, 0, m, kt_out, lane)];
                u32* fwL = (u32*)&frag[fidx(cur, 1, m, kt_out, lane)];
                #pragma unroll
                for (int rh = 0; rh < 2; rh++) {
                    int row = m * 16 + (lane >> 2) + rh * 8;
                    float2 hp = *(float2*)&hm[row * HMS + u];
                    float hA = hp.x + cA;
                    float hB = hp.y + cB;
                    *(float2*)&hm[row * HMS + u] = make_float2(hA, hB);
                    fwH[rh + 2 * t] = packbf(hA, hB);
                    fwL[rh + 2 * t] = packbf(bf16res(hA), bf16res(hB));
                }
            }
        }
    }
    if (tid < RPB) {
        const float* p = traj + (((size_t)b * TT + (TT - 1)) * OO + o0 + tid) * 2;
        stt[tid * 2]     = p[0];
        stt[tid * 2 + 1] = p[1];
    }
    __syncthreads();
    // decoder tables
    for (int i = tid; i < HD * 12; i += NTH) gtab[i] = scr_GI_cell[i];
    for (int i = tid; i < HD; i += NTH)      aux[i] = b1g[i];
    for (int i = tid; i < 2 * HD; i += NTH)  aux[HD + i] = W2g[i];
    if (tid < 2) aux[3 * HD + tid] = b2g[tid];
    __syncthreads();

    // ---------------- decoder: 48 steps ----------------
    for (int s = 0; s < HOR; s++) {
        gru_step_mma(cur, frag, hm, gtab, stt, scr_Wf_cell, warp, lane);
        cur ^= 1;
        __syncthreads();

        // act scratch overlays the dead frag parity (old h)
        float* act = (float*)(smc + (cur ^ 1) * 65536);

        // h1 = gelu(h @ W1.T + b1) via mma; A = frag parity cur
        #pragma unroll 1
        for (int uc = 0; uc < 2; uc++) {
            int T0 = warp * 4 + uc * 2;
            float d[2][2][4];
            #pragma unroll
            for (int t = 0; t < 2; t++)
                #pragma unroll
                for (int m = 0; m < 2; m++)
                    #pragma unroll
                    for (int c = 0; c < 4; c++) d[t][m][c] = 0.f;
            #pragma unroll 1
            for (int kt = 0; kt < 32; kt++) {
                uint4 aH0 = frag[fidx(cur, 0, 0, kt, lane)];
                uint4 aL0 = frag[fidx(cur, 1, 0, kt, lane)];
                uint4 aH1 = frag[fidx(cur, 0, 1, kt, lane)];
                uint4 aL1 = frag[fidx(cur, 1, 1, kt, lane)];
                #pragma unroll
                for (int t = 0; t < 2; t++) {
                    uint4 w = scr_Wf_w1[(((size_t)(T0 + t)) * 32 + kt) * 32 + lane];
                    mma16816(d[t][0], aH0, w.x, w.y);
                    mma16816(d[t][0], aH0, w.z, w.w);
                    mma16816(d[t][0], aL0, w.x, w.y);
                    mma16816(d[t][1], aH1, w.x, w.y);
                    mma16816(d[t][1], aH1, w.z, w.w);
                    mma16816(d[t][1], aL1, w.x, w.y);
                }
            }
            #pragma unroll
            for (int t = 0; t < 2; t++) {
                int u = (T0 + t) * 8 + (lane & 3) * 2;
                float b1A = aux[u], b1B = aux[u + 1];
                #pragma unroll
                for (int m = 0; m < 2; m++) {
                    #pragma unroll
                    for (int rh = 0; rh < 2; rh++) {
                        int row = m * 16 + (lane >> 2) + rh * 8;
                        float v0 = d[t][m][rh*2+0] + b1A;
                        float v1 = d[t][m][rh*2+1] + b1B;
                        float g0 = 0.5f * v0 * (1.f + erff(v0 * 0.7071067811865475f));
                        float g1 = 0.5f * v1 * (1.f + erff(v1 * 0.7071067811865475f));
                        *(float2*)&act[actIdx(row, u)] = make_float2(g0, g1);
                    }
                }
            }
        }
        __syncthreads();

        // d = h1 @ W2.T + b2 ; clamp/step/wrap ; emit  (16 warps x 2 rows)
        #pragma unroll
        for (int r = 0; r < 2; r++) {
            int row = warp * 2 + r;
            float s0 = 0.f, s1 = 0.f;
            #pragma unroll
            for (int k = lane; k < HD; k += 32) {
                float hv = act[actIdx(row, k)];
                s0 = fmaf(hv, aux[HD + k],     s0);
                s1 = fmaf(hv, aux[2 * HD + k], s1);
            }
            #pragma unroll
            for (int off = 16; off; off >>= 1) {
                s0 += __shfl_down_sync(0xffffffffu, s0, off);
                s1 += __shfl_down_sync(0xffffffffu, s1, off);
            }
            if (lane == 0) {
                float d0 = s0 + aux[3 * HD];
                float d1 = s1 + aux[3 * HD + 1];
                d0 = 2.f * tanhf(d0 * 0.5f);
                d1 = 2.f * tanhf(d1 * 0.5f);
                float n0 = stt[row * 2]     + d0;
                float n1 = stt[row * 2 + 1] + d1;
                n0 = fminf(fmaxf(n0, -90.f), 90.f);
                float m = fmodf(n1, 360.f);
                if (m < 0.f) m += 360.f;
                stt[row * 2]     = n0;
                stt[row * 2 + 1] = m;
                size_t oo = (((size_t)b * HOR + s) * OO + (o0 + row)) * 2;
                out[oo]     = n0;
                out[oo + 1] = m;
            }
        }
        __syncthreads();
    }
}

// ---------------- launch ----------------
extern "C" void kernel_launch(void* const* d_in, const int* in_sizes, int n_in,
                              void* d_out, int out_size) {
    (void)in_sizes; (void)n_in; (void)out_size;
    const float* z_ctx   = (const float*)d_in[0];
    const float* traj    = (const float*)d_in[1];
    const float* W_emb   = (const float*)d_in[2];
    const float* b_emb   = (const float*)d_in[3];
    const float* W_ctx   = (const float*)d_in[4];
    const float* b_ctx   = (const float*)d_in[5];
    const float* Wi_enc  = (const float*)d_in[6];
    const float* Wh_enc  = (const float*)d_in[7];
    const float* bi_enc  = (const float*)d_in[8];
    const float* bh_enc  = (const float*)d_in[9];
    const float* Wi_cell = (const float*)d_in[10];
    const float* Wh_cell = (const float*)d_in[11];
    const float* bi_cell = (const float*)d_in[12];
    const float* bh_cell = (const float*)d_in[13];
    const float* W1      = (const float*)d_in[14];
    const float* b1      = (const float*)d_in[15];
    const float* W2      = (const float*)d_in[16];
    const float* b2      = (const float*)d_in[17];
    float* out = (float*)d_out;

    prep_wfrag<<<1792, 256>>>(Wh_enc, Wh_cell, W1);
    prep_gi<<<384, 256>>>(Wi_enc, bi_enc, bh_enc, Wi_cell, bi_cell, bh_cell, W_emb, b_emb);
    prep_ctx<<<64, 256>>>(z_ctx, W_ctx, b_ctx);

    cudaFuncSetAttribute(traj_main, cudaFuncAttributeMaxDynamicSharedMemorySize, SMEM_BYTES);
    traj_main<<<NBLK, NTH, SMEM_BYTES>>>(traj, b1, W2, b2, out);
}